// round 3
// baseline (speedup 1.0000x reference)
#include <cuda_runtime.h>
#include <math.h>

namespace {

constexpr int B  = 4;
constexpr int N  = 2048;
constexpr int D  = 1024;
constexpr int H  = 16;
constexpr int HD = 64;
constexpr int RD = 32;
constexpr int M  = B * N;   // 8192

// -------- scratch (device globals: allocation-guard safe) --------
__device__ float g_q[M * D];
__device__ float g_k[M * D];
__device__ float g_v[M * D];
__device__ float g_o[M * D];

// ================= SGEMM (A[MxK] * W[KxN] + bias) =================
constexpr int BM = 128, BN = 128, BK = 8;

__global__ __launch_bounds__(256) void sgemm_bias_kernel(
    const float* __restrict__ A, const float* __restrict__ W,
    const float* __restrict__ bias, float* __restrict__ C,
    int Md, int Nd, int Kd)
{
    __shared__ float As[BK][BM];
    __shared__ float Bs[BK][BN];

    const int tid  = threadIdx.x;
    const int brow = blockIdx.y;
    const int bcol = blockIdx.x;
    const int ty   = tid >> 4;     // 0..15
    const int tx   = tid & 15;     // 0..15

    float acc[8][8];
#pragma unroll
    for (int i = 0; i < 8; i++)
#pragma unroll
        for (int j = 0; j < 8; j++) acc[i][j] = 0.0f;

    const int aRow = tid >> 1;          // 0..127
    const int aCol = (tid & 1) * 4;     // 0 or 4
    const int bRow = tid >> 5;          // 0..7
    const int bCol = (tid & 31) * 4;    // 0..124

    const float* Aptr = A + (size_t)(brow * BM) * Kd;
    const float* Wptr = W + bcol * BN;

    for (int k0 = 0; k0 < Kd; k0 += BK) {
        float4 av = *(const float4*)(Aptr + (size_t)aRow * Kd + k0 + aCol);
        As[aCol + 0][aRow] = av.x;
        As[aCol + 1][aRow] = av.y;
        As[aCol + 2][aRow] = av.z;
        As[aCol + 3][aRow] = av.w;

        float4 wv = *(const float4*)(Wptr + (size_t)(k0 + bRow) * Nd + bCol);
        *(float4*)&Bs[bRow][bCol] = wv;

        __syncthreads();

#pragma unroll
        for (int k = 0; k < BK; k++) {
            float a[8], b[8];
#pragma unroll
            for (int i = 0; i < 8; i++) a[i] = As[k][ty * 8 + i];
#pragma unroll
            for (int j = 0; j < 8; j++) b[j] = Bs[k][tx * 8 + j];
#pragma unroll
            for (int i = 0; i < 8; i++)
#pragma unroll
                for (int j = 0; j < 8; j++) acc[i][j] = fmaf(a[i], b[j], acc[i][j]);
        }
        __syncthreads();
    }

    // epilogue: bias + store (float4)
#pragma unroll
    for (int i = 0; i < 8; i++) {
        const size_t row = (size_t)(brow * BM + ty * 8 + i);
        float* crow = C + row * Nd + bcol * BN + tx * 8;
        const float* brow_b = bias + bcol * BN + tx * 8;
        float4 v0, v1;
        v0.x = acc[i][0] + brow_b[0];
        v0.y = acc[i][1] + brow_b[1];
        v0.z = acc[i][2] + brow_b[2];
        v0.w = acc[i][3] + brow_b[3];
        v1.x = acc[i][4] + brow_b[4];
        v1.y = acc[i][5] + brow_b[5];
        v1.z = acc[i][6] + brow_b[6];
        v1.w = acc[i][7] + brow_b[7];
        *(float4*)(crow + 0) = v0;
        *(float4*)(crow + 4) = v1;
    }
}

// ================= RoPE (rotation only; q scale applied in flash) =================
// q layout: [B, N, H, HD] flattened as (b*N+n)*D + h*HD + d
__global__ void rope_kernel(float* __restrict__ q, float* __restrict__ k,
                            const float* __restrict__ pos_enc)
{
    const int total = B * N * H * (RD / 2);
    int idx = blockIdx.x * blockDim.x + threadIdx.x;
    if (idx >= total) return;

    const int p = idx % (RD / 2);
    const int h = (idx / (RD / 2)) % H;
    const int n = (idx / ((RD / 2) * H)) % N;
    const int b = idx / ((RD / 2) * H * N);

    const float pe0 = pos_enc[n * RD + 2 * p];
    const float pe1 = pos_enc[n * RD + 2 * p + 1];
    const float c0 = cosf(pe0), s0 = sinf(pe0);
    const float c1 = cosf(pe1), s1 = sinf(pe1);

    const size_t base = ((size_t)(b * N + n)) * D + h * HD + 2 * p;

    float q0 = q[base], q1 = q[base + 1];
    q[base]     = q0 * c0 - q1 * s0;
    q[base + 1] = q1 * c1 + q0 * s1;

    float k0 = k[base], k1 = k[base + 1];
    k[base]     = k0 * c0 - k1 * s0;
    k[base + 1] = k1 * c1 + k0 * s1;
}

// ================= Flash attention (fp32, causal) =================
constexpr int FBM = 64;     // q rows per block
constexpr int FBN = 64;     // keys per tile
constexpr int SPAD = 65;    // smem row stride (bank-conflict pad)
constexpr int FLASH_SMEM = 4 * FBM * SPAD * (int)sizeof(float);  // Q,K,V,P

__global__ __launch_bounds__(128) void flash_kernel(
    const float* __restrict__ q, const float* __restrict__ k,
    const float* __restrict__ v, const unsigned char* __restrict__ pad,
    float* __restrict__ o)
{
    extern __shared__ float sm[];
    float* Qs = sm;                    // [FBM][SPAD]
    float* Ks = Qs + FBM * SPAD;       // [FBN][SPAD]
    float* Vs = Ks + FBN * SPAD;       // [FBN][SPAD]
    float* Ps = Vs + FBN * SPAD;       // [FBM][SPAD]

    const int qt = blockIdx.x;
    const int h  = blockIdx.y;
    const int b  = blockIdx.z;
    const int qi0 = qt * FBM;

    const int tid = threadIdx.x;       // 128
    const int tx = tid & 15;           // col group
    const int ty = tid >> 4;           // 0..7, row group

    // load Q tile, applying the HD^-0.5 scale to ALL dims (rotation commutes
    // with scalar scale, so post-RoPE scaling matches the reference's
    // pre-RoPE scaling; crucially it also scales the pass-through dims)
    const float qscale = 0.125f;  // HD^-0.5
    const size_t qbase = ((size_t)(b * N + qi0)) * D + h * HD;
    for (int idx = tid; idx < FBM * HD; idx += 128) {
        const int r = idx >> 6, c = idx & 63;
        Qs[r * SPAD + c] = q[qbase + (size_t)r * D + c] * qscale;
    }

    float m_i[8], l_i[8], oacc[8][4];
#pragma unroll
    for (int i = 0; i < 8; i++) {
        m_i[i] = -1e30f;
        l_i[i] = 0.0f;
#pragma unroll
        for (int j = 0; j < 4; j++) oacc[i][j] = 0.0f;
    }
    __syncthreads();

    const int ktiles = qt + 1;  // causal: skip fully-masked tiles
    for (int kt = 0; kt < ktiles; kt++) {
        const int kj0 = kt * FBN;
        const size_t kbase = ((size_t)(b * N + kj0)) * D + h * HD;
        for (int idx = tid; idx < FBN * HD; idx += 128) {
            const int r = idx >> 6, c = idx & 63;
            Ks[r * SPAD + c] = k[kbase + (size_t)r * D + c];
            Vs[r * SPAD + c] = v[kbase + (size_t)r * D + c];
        }
        __syncthreads();

        // S = Q K^T  (rows ty*8+i, cols tx+16*j)
        float s[8][4];
#pragma unroll
        for (int i = 0; i < 8; i++)
#pragma unroll
            for (int j = 0; j < 4; j++) s[i][j] = 0.0f;

        for (int d = 0; d < HD; d++) {
            float a[8], bb[4];
#pragma unroll
            for (int i = 0; i < 8; i++) a[i] = Qs[(ty * 8 + i) * SPAD + d];
#pragma unroll
            for (int j = 0; j < 4; j++) bb[j] = Ks[(tx + 16 * j) * SPAD + d];
#pragma unroll
            for (int i = 0; i < 8; i++)
#pragma unroll
                for (int j = 0; j < 4; j++) s[i][j] = fmaf(a[i], bb[j], s[i][j]);
        }

        // mask: causal + pad
#pragma unroll
        for (int j = 0; j < 4; j++) {
            const int kcol = kj0 + tx + 16 * j;
            const bool padm = pad[b * N + kcol] != 0;
#pragma unroll
            for (int i = 0; i < 8; i++) {
                const int qrow = qi0 + ty * 8 + i;
                if (padm || kcol > qrow) s[i][j] = -1e30f;
            }
        }

        // online softmax (reduce across the 16 tx lanes; warp-half shuffles)
#pragma unroll
        for (int i = 0; i < 8; i++) {
            float mx = s[i][0];
#pragma unroll
            for (int j = 1; j < 4; j++) mx = fmaxf(mx, s[i][j]);
#pragma unroll
            for (int off = 8; off >= 1; off >>= 1)
                mx = fmaxf(mx, __shfl_xor_sync(0xffffffffu, mx, off));
            const float mnew = fmaxf(m_i[i], mx);
            const float alpha = __expf(m_i[i] - mnew);
            m_i[i] = mnew;

            float rsum = 0.0f;
#pragma unroll
            for (int j = 0; j < 4; j++) {
                s[i][j] = __expf(s[i][j] - mnew);
                rsum += s[i][j];
            }
#pragma unroll
            for (int off = 8; off >= 1; off >>= 1)
                rsum += __shfl_xor_sync(0xffffffffu, rsum, off);
            l_i[i] = l_i[i] * alpha + rsum;

#pragma unroll
            for (int j = 0; j < 4; j++) {
                oacc[i][j] *= alpha;
                Ps[(ty * 8 + i) * SPAD + (tx + 16 * j)] = s[i][j];
            }
        }
        __syncwarp();  // P rows for a ty-group live within one warp half

        // O += P V
        for (int kk = 0; kk < FBN; kk++) {
            float pv[8], vv[4];
#pragma unroll
            for (int i = 0; i < 8; i++) pv[i] = Ps[(ty * 8 + i) * SPAD + kk];
#pragma unroll
            for (int j = 0; j < 4; j++) vv[j] = Vs[kk * SPAD + tx + 16 * j];
#pragma unroll
            for (int i = 0; i < 8; i++)
#pragma unroll
                for (int j = 0; j < 4; j++) oacc[i][j] = fmaf(pv[i], vv[j], oacc[i][j]);
        }
        __syncthreads();  // done with Ks/Vs/Ps before next tile load
    }

    // write O (divide by l)
#pragma unroll
    for (int i = 0; i < 8; i++) {
        const float inv_l = 1.0f / l_i[i];
        const size_t obase = ((size_t)(b * N + qi0 + ty * 8 + i)) * D + h * HD;
#pragma unroll
        for (int j = 0; j < 4; j++)
            o[obase + tx + 16 * j] = oacc[i][j] * inv_l;
    }
}

}  // namespace

extern "C" void kernel_launch(void* const* d_in, const int* in_sizes, int n_in,
                              void* d_out, int out_size)
{
    const float* x_q  = (const float*)d_in[0];
    const float* x_kv = (const float*)d_in[1];
    const float* pos_enc = (const float*)d_in[2];
    const float* Wq = (const float*)d_in[3];
    const float* bq = (const float*)d_in[4];
    const float* Wk = (const float*)d_in[5];
    const float* bk = (const float*)d_in[6];
    const float* Wv = (const float*)d_in[7];
    const float* bv = (const float*)d_in[8];
    const float* Wo = (const float*)d_in[9];
    const float* bo = (const float*)d_in[10];
    const unsigned char* pad = (const unsigned char*)d_in[11];
    float* out = (float*)d_out;

    float *q, *k, *v, *o;
    cudaGetSymbolAddress((void**)&q, g_q);
    cudaGetSymbolAddress((void**)&k, g_k);
    cudaGetSymbolAddress((void**)&v, g_v);
    cudaGetSymbolAddress((void**)&o, g_o);

    const dim3 gemm_grid(D / BN, M / BM);  // (8, 64)

    sgemm_bias_kernel<<<gemm_grid, 256>>>(x_q,  Wq, bq, q, M, D, D);
    sgemm_bias_kernel<<<gemm_grid, 256>>>(x_kv, Wk, bk, k, M, D, D);
    sgemm_bias_kernel<<<gemm_grid, 256>>>(x_kv, Wv, bv, v, M, D, D);

    const int rope_total = B * N * H * (RD / 2);
    rope_kernel<<<(rope_total + 255) / 256, 256>>>(q, k, pos_enc);

    cudaFuncSetAttribute(flash_kernel,
                         cudaFuncAttributeMaxDynamicSharedMemorySize, FLASH_SMEM);
    flash_kernel<<<dim3(N / FBM, H, B), 128, FLASH_SMEM>>>(q, k, v, pad, o);

    sgemm_bias_kernel<<<gemm_grid, 256>>>(o, Wo, bo, out, M, D, D);
}

// round 4
// speedup vs baseline: 1.4537x; 1.4537x over previous
#include <cuda_runtime.h>
#include <math.h>
#include <stdint.h>

namespace {

constexpr int B  = 4;
constexpr int N  = 2048;
constexpr int D  = 1024;
constexpr int H  = 16;
constexpr int HD = 64;
constexpr int RD = 32;
constexpr int M  = B * N;   // 8192

// -------- scratch (device globals: allocation-guard safe) --------
__device__ float g_q[M * D];
__device__ float g_k[M * D];
__device__ float g_v[M * D];
__device__ float g_o[M * D];

// ================= TF32 tensor-core GEMM (A[MxK] * W[KxN] + bias) =========
// 128x128x16 block tile, 256 threads (8 warps), warp tile 64x32,
// mma.sync m16n8k8 tf32, fp32 accumulate, fused bias epilogue.
constexpr int TBM = 128, TBN = 128, TBK = 16;
constexpr int SSTR = TBN + 4;   // 132, %4==0 so float4 stores stay aligned

__device__ __forceinline__ uint32_t f32_to_tf32(float x) {
    uint32_t y;
    asm("cvt.rna.tf32.f32 %0, %1;" : "=r"(y) : "f"(x));
    return y;
}

__device__ __forceinline__ void mma_tf32(
    float& d0, float& d1, float& d2, float& d3,
    uint32_t a0, uint32_t a1, uint32_t a2, uint32_t a3,
    uint32_t b0, uint32_t b1)
{
    asm volatile(
        "mma.sync.aligned.m16n8k8.row.col.f32.tf32.tf32.f32 "
        "{%0,%1,%2,%3}, {%4,%5,%6,%7}, {%8,%9}, {%0,%1,%2,%3};"
        : "+f"(d0), "+f"(d1), "+f"(d2), "+f"(d3)
        : "r"(a0), "r"(a1), "r"(a2), "r"(a3), "r"(b0), "r"(b1));
}

__global__ __launch_bounds__(256) void tf32_gemm_bias_kernel(
    const float* __restrict__ A, const float* __restrict__ W,
    const float* __restrict__ bias, float* __restrict__ C,
    int Nd, int Kd)
{
    __shared__ uint32_t As[TBK][TBM + 4];   // [k][m] (transposed)
    __shared__ uint32_t Bs[TBK][SSTR];      // [k][n]

    const int tid  = threadIdx.x;
    const int wid  = tid >> 5;
    const int lane = tid & 31;
    const int g    = lane >> 2;      // groupID (row within 8)
    const int tig  = lane & 3;       // thread-in-group

    const int warp_m = (wid >> 2) * 64;   // 0 or 64
    const int warp_n = (wid & 3) * 32;    // 0,32,64,96

    const int brow0 = blockIdx.y * TBM;
    const int bcol0 = blockIdx.x * TBN;

    float acc[4][4][4];
#pragma unroll
    for (int mt = 0; mt < 4; mt++)
#pragma unroll
        for (int nt = 0; nt < 4; nt++)
#pragma unroll
            for (int r = 0; r < 4; r++) acc[mt][nt][r] = 0.0f;

    // A tile loader: 128 rows x 16 cols = 512 float4; 2 per thread
    // fid = tid + i*256 : aRow = fid/4, aCol = (fid%4)*4
    // B tile loader: 16 rows x 128 cols = 512 float4; 2 per thread
    // fid : bRow = fid/32, bCol = (fid%32)*4
    const float* Aptr = A + (size_t)brow0 * Kd;
    const float* Wptr = W + bcol0;

    for (int k0 = 0; k0 < Kd; k0 += TBK) {
#pragma unroll
        for (int i = 0; i < 2; i++) {
            const int fid = tid + i * 256;
            const int aRow = fid >> 2, aCol = (fid & 3) * 4;
            float4 av = *(const float4*)(Aptr + (size_t)aRow * Kd + k0 + aCol);
            As[aCol + 0][aRow] = f32_to_tf32(av.x);
            As[aCol + 1][aRow] = f32_to_tf32(av.y);
            As[aCol + 2][aRow] = f32_to_tf32(av.z);
            As[aCol + 3][aRow] = f32_to_tf32(av.w);

            const int bRow = fid >> 5, bCol = (fid & 31) * 4;
            float4 wv = *(const float4*)(Wptr + (size_t)(k0 + bRow) * Nd + bCol);
            uint4 tv;
            tv.x = f32_to_tf32(wv.x);
            tv.y = f32_to_tf32(wv.y);
            tv.z = f32_to_tf32(wv.z);
            tv.w = f32_to_tf32(wv.w);
            *(uint4*)&Bs[bRow][bCol] = tv;
        }
        __syncthreads();

#pragma unroll
        for (int kk = 0; kk < TBK; kk += 8) {
            uint32_t af[4][4], bf[4][2];
#pragma unroll
            for (int mt = 0; mt < 4; mt++) {
                const int rm = warp_m + mt * 16;
                af[mt][0] = As[kk + tig    ][rm + g    ];
                af[mt][1] = As[kk + tig    ][rm + g + 8];
                af[mt][2] = As[kk + tig + 4][rm + g    ];
                af[mt][3] = As[kk + tig + 4][rm + g + 8];
            }
#pragma unroll
            for (int nt = 0; nt < 4; nt++) {
                const int cn = warp_n + nt * 8;
                bf[nt][0] = Bs[kk + tig    ][cn + g];
                bf[nt][1] = Bs[kk + tig + 4][cn + g];
            }
#pragma unroll
            for (int mt = 0; mt < 4; mt++)
#pragma unroll
                for (int nt = 0; nt < 4; nt++)
                    mma_tf32(acc[mt][nt][0], acc[mt][nt][1],
                             acc[mt][nt][2], acc[mt][nt][3],
                             af[mt][0], af[mt][1], af[mt][2], af[mt][3],
                             bf[nt][0], bf[nt][1]);
        }
        __syncthreads();
    }

    // epilogue: bias + store.
    // c0=C[g][tig*2], c1=C[g][tig*2+1], c2=C[g+8][tig*2], c3=C[g+8][tig*2+1]
#pragma unroll
    for (int mt = 0; mt < 4; mt++) {
#pragma unroll
        for (int nt = 0; nt < 4; nt++) {
            const int col = bcol0 + warp_n + nt * 8 + tig * 2;
            const float b0 = bias[col], b1 = bias[col + 1];
            const size_t r0 = (size_t)(brow0 + warp_m + mt * 16 + g);
            const size_t r1 = r0 + 8;
            float2 v0 = make_float2(acc[mt][nt][0] + b0, acc[mt][nt][1] + b1);
            float2 v1 = make_float2(acc[mt][nt][2] + b0, acc[mt][nt][3] + b1);
            *(float2*)(C + r0 * Nd + col) = v0;
            *(float2*)(C + r1 * Nd + col) = v1;
        }
    }
}

// ================= RoPE (rotation only; q scale applied in flash) =================
__global__ void rope_kernel(float* __restrict__ q, float* __restrict__ k,
                            const float* __restrict__ pos_enc)
{
    const int total = B * N * H * (RD / 2);
    int idx = blockIdx.x * blockDim.x + threadIdx.x;
    if (idx >= total) return;

    const int p = idx % (RD / 2);
    const int h = (idx / (RD / 2)) % H;
    const int n = (idx / ((RD / 2) * H)) % N;
    const int b = idx / ((RD / 2) * H * N);

    const float pe0 = pos_enc[n * RD + 2 * p];
    const float pe1 = pos_enc[n * RD + 2 * p + 1];
    const float c0 = cosf(pe0), s0 = sinf(pe0);
    const float c1 = cosf(pe1), s1 = sinf(pe1);

    const size_t base = ((size_t)(b * N + n)) * D + h * HD + 2 * p;

    float q0 = q[base], q1 = q[base + 1];
    q[base]     = q0 * c0 - q1 * s0;
    q[base + 1] = q1 * c1 + q0 * s1;

    float k0 = k[base], k1 = k[base + 1];
    k[base]     = k0 * c0 - k1 * s0;
    k[base + 1] = k1 * c1 + k0 * s1;
}

// ================= Flash attention (fp32, causal) =================
constexpr int FBM = 64;
constexpr int FBN = 64;
constexpr int SPAD = 65;
constexpr int FLASH_SMEM = 4 * FBM * SPAD * (int)sizeof(float);

__global__ __launch_bounds__(128) void flash_kernel(
    const float* __restrict__ q, const float* __restrict__ k,
    const float* __restrict__ v, const unsigned char* __restrict__ pad,
    float* __restrict__ o)
{
    extern __shared__ float sm[];
    float* Qs = sm;
    float* Ks = Qs + FBM * SPAD;
    float* Vs = Ks + FBN * SPAD;
    float* Ps = Vs + FBN * SPAD;

    const int qt = blockIdx.x;
    const int h  = blockIdx.y;
    const int b  = blockIdx.z;
    const int qi0 = qt * FBM;

    const int tid = threadIdx.x;
    const int tx = tid & 15;
    const int ty = tid >> 4;

    const float qscale = 0.125f;
    const size_t qbase = ((size_t)(b * N + qi0)) * D + h * HD;
    for (int idx = tid; idx < FBM * HD; idx += 128) {
        const int r = idx >> 6, c = idx & 63;
        Qs[r * SPAD + c] = q[qbase + (size_t)r * D + c] * qscale;
    }

    float m_i[8], l_i[8], oacc[8][4];
#pragma unroll
    for (int i = 0; i < 8; i++) {
        m_i[i] = -1e30f;
        l_i[i] = 0.0f;
#pragma unroll
        for (int j = 0; j < 4; j++) oacc[i][j] = 0.0f;
    }
    __syncthreads();

    const int ktiles = qt + 1;
    for (int kt = 0; kt < ktiles; kt++) {
        const int kj0 = kt * FBN;
        const size_t kbase = ((size_t)(b * N + kj0)) * D + h * HD;
        for (int idx = tid; idx < FBN * HD; idx += 128) {
            const int r = idx >> 6, c = idx & 63;
            Ks[r * SPAD + c] = k[kbase + (size_t)r * D + c];
            Vs[r * SPAD + c] = v[kbase + (size_t)r * D + c];
        }
        __syncthreads();

        float s[8][4];
#pragma unroll
        for (int i = 0; i < 8; i++)
#pragma unroll
            for (int j = 0; j < 4; j++) s[i][j] = 0.0f;

        for (int d = 0; d < HD; d++) {
            float a[8], bb[4];
#pragma unroll
            for (int i = 0; i < 8; i++) a[i] = Qs[(ty * 8 + i) * SPAD + d];
#pragma unroll
            for (int j = 0; j < 4; j++) bb[j] = Ks[(tx + 16 * j) * SPAD + d];
#pragma unroll
            for (int i = 0; i < 8; i++)
#pragma unroll
                for (int j = 0; j < 4; j++) s[i][j] = fmaf(a[i], bb[j], s[i][j]);
        }

#pragma unroll
        for (int j = 0; j < 4; j++) {
            const int kcol = kj0 + tx + 16 * j;
            const bool padm = pad[b * N + kcol] != 0;
#pragma unroll
            for (int i = 0; i < 8; i++) {
                const int qrow = qi0 + ty * 8 + i;
                if (padm || kcol > qrow) s[i][j] = -1e30f;
            }
        }

#pragma unroll
        for (int i = 0; i < 8; i++) {
            float mx = s[i][0];
#pragma unroll
            for (int j = 1; j < 4; j++) mx = fmaxf(mx, s[i][j]);
#pragma unroll
            for (int off = 8; off >= 1; off >>= 1)
                mx = fmaxf(mx, __shfl_xor_sync(0xffffffffu, mx, off));
            const float mnew = fmaxf(m_i[i], mx);
            const float alpha = __expf(m_i[i] - mnew);
            m_i[i] = mnew;

            float rsum = 0.0f;
#pragma unroll
            for (int j = 0; j < 4; j++) {
                s[i][j] = __expf(s[i][j] - mnew);
                rsum += s[i][j];
            }
#pragma unroll
            for (int off = 8; off >= 1; off >>= 1)
                rsum += __shfl_xor_sync(0xffffffffu, rsum, off);
            l_i[i] = l_i[i] * alpha + rsum;

#pragma unroll
            for (int j = 0; j < 4; j++) {
                oacc[i][j] *= alpha;
                Ps[(ty * 8 + i) * SPAD + (tx + 16 * j)] = s[i][j];
            }
        }
        __syncwarp();

        for (int kk = 0; kk < FBN; kk++) {
            float pv[8], vv[4];
#pragma unroll
            for (int i = 0; i < 8; i++) pv[i] = Ps[(ty * 8 + i) * SPAD + kk];
#pragma unroll
            for (int j = 0; j < 4; j++) vv[j] = Vs[kk * SPAD + tx + 16 * j];
#pragma unroll
            for (int i = 0; i < 8; i++)
#pragma unroll
                for (int j = 0; j < 4; j++) oacc[i][j] = fmaf(pv[i], vv[j], oacc[i][j]);
        }
        __syncthreads();
    }

#pragma unroll
    for (int i = 0; i < 8; i++) {
        const float inv_l = 1.0f / l_i[i];
        const size_t obase = ((size_t)(b * N + qi0 + ty * 8 + i)) * D + h * HD;
#pragma unroll
        for (int j = 0; j < 4; j++)
            o[obase + tx + 16 * j] = oacc[i][j] * inv_l;
    }
}

}  // namespace

extern "C" void kernel_launch(void* const* d_in, const int* in_sizes, int n_in,
                              void* d_out, int out_size)
{
    const float* x_q  = (const float*)d_in[0];
    const float* x_kv = (const float*)d_in[1];
    const float* pos_enc = (const float*)d_in[2];
    const float* Wq = (const float*)d_in[3];
    const float* bq = (const float*)d_in[4];
    const float* Wk = (const float*)d_in[5];
    const float* bk = (const float*)d_in[6];
    const float* Wv = (const float*)d_in[7];
    const float* bv = (const float*)d_in[8];
    const float* Wo = (const float*)d_in[9];
    const float* bo = (const float*)d_in[10];
    const unsigned char* pad = (const unsigned char*)d_in[11];
    float* out = (float*)d_out;

    float *q, *k, *v, *o;
    cudaGetSymbolAddress((void**)&q, g_q);
    cudaGetSymbolAddress((void**)&k, g_k);
    cudaGetSymbolAddress((void**)&v, g_v);
    cudaGetSymbolAddress((void**)&o, g_o);

    const dim3 gemm_grid(D / TBN, M / TBM);  // (8, 64)

    tf32_gemm_bias_kernel<<<gemm_grid, 256>>>(x_q,  Wq, bq, q, D, D);
    tf32_gemm_bias_kernel<<<gemm_grid, 256>>>(x_kv, Wk, bk, k, D, D);
    tf32_gemm_bias_kernel<<<gemm_grid, 256>>>(x_kv, Wv, bv, v, D, D);

    const int rope_total = B * N * H * (RD / 2);
    rope_kernel<<<(rope_total + 255) / 256, 256>>>(q, k, pos_enc);

    cudaFuncSetAttribute(flash_kernel,
                         cudaFuncAttributeMaxDynamicSharedMemorySize, FLASH_SMEM);
    flash_kernel<<<dim3(N / FBM, H, B), 128, FLASH_SMEM>>>(q, k, v, pad, o);

    tf32_gemm_bias_kernel<<<gemm_grid, 256>>>(o, Wo, bo, out, D, D);
}

// round 8
// speedup vs baseline: 2.0264x; 1.3940x over previous
#include <cuda_runtime.h>
#include <math.h>
#include <stdint.h>

namespace {

constexpr int B  = 4;
constexpr int N  = 2048;
constexpr int D  = 1024;
constexpr int H  = 16;
constexpr int HD = 64;
constexpr int RD = 32;
constexpr int M  = B * N;   // 8192

// -------- scratch (device globals: allocation-guard safe) --------
__device__ float g_q[M * D];
__device__ float g_k[M * D];
__device__ float g_v[M * D];
__device__ float g_o[M * D];

__device__ __forceinline__ uint32_t f32_to_tf32(float x) {
    uint32_t y;
    asm("cvt.rna.tf32.f32 %0, %1;" : "=r"(y) : "f"(x));
    return y;
}

__device__ __forceinline__ void mma_tf32(
    float& d0, float& d1, float& d2, float& d3,
    uint32_t a0, uint32_t a1, uint32_t a2, uint32_t a3,
    uint32_t b0, uint32_t b1)
{
    asm volatile(
        "mma.sync.aligned.m16n8k8.row.col.f32.tf32.tf32.f32 "
        "{%0,%1,%2,%3}, {%4,%5,%6,%7}, {%8,%9}, {%0,%1,%2,%3};"
        : "+f"(d0), "+f"(d1), "+f"(d2), "+f"(d3)
        : "r"(a0), "r"(a1), "r"(a2), "r"(a3), "r"(b0), "r"(b1));
}

// ================= TF32 tensor-core GEMM (A[MxK] * W[KxN] + bias) =========
constexpr int TBM = 128, TBN = 128, TBK = 16;
constexpr int SSTR = TBN + 4;

__global__ __launch_bounds__(256) void tf32_gemm_bias_kernel(
    const float* __restrict__ A, const float* __restrict__ W,
    const float* __restrict__ bias, float* __restrict__ C,
    int Nd, int Kd)
{
    __shared__ uint32_t As[TBK][TBM + 4];
    __shared__ uint32_t Bs[TBK][SSTR];

    const int tid  = threadIdx.x;
    const int wid  = tid >> 5;
    const int lane = tid & 31;
    const int g    = lane >> 2;
    const int tig  = lane & 3;

    const int warp_m = (wid >> 2) * 64;
    const int warp_n = (wid & 3) * 32;

    const int brow0 = blockIdx.y * TBM;
    const int bcol0 = blockIdx.x * TBN;

    float acc[4][4][4];
#pragma unroll
    for (int mt = 0; mt < 4; mt++)
#pragma unroll
        for (int nt = 0; nt < 4; nt++)
#pragma unroll
            for (int r = 0; r < 4; r++) acc[mt][nt][r] = 0.0f;

    const float* Aptr = A + (size_t)brow0 * Kd;
    const float* Wptr = W + bcol0;

    for (int k0 = 0; k0 < Kd; k0 += TBK) {
#pragma unroll
        for (int i = 0; i < 2; i++) {
            const int fid = tid + i * 256;
            const int aRow = fid >> 2, aCol = (fid & 3) * 4;
            float4 av = *(const float4*)(Aptr + (size_t)aRow * Kd + k0 + aCol);
            As[aCol + 0][aRow] = f32_to_tf32(av.x);
            As[aCol + 1][aRow] = f32_to_tf32(av.y);
            As[aCol + 2][aRow] = f32_to_tf32(av.z);
            As[aCol + 3][aRow] = f32_to_tf32(av.w);

            const int bRow = fid >> 5, bCol = (fid & 31) * 4;
            float4 wv = *(const float4*)(Wptr + (size_t)(k0 + bRow) * Nd + bCol);
            uint4 tv;
            tv.x = f32_to_tf32(wv.x);
            tv.y = f32_to_tf32(wv.y);
            tv.z = f32_to_tf32(wv.z);
            tv.w = f32_to_tf32(wv.w);
            *(uint4*)&Bs[bRow][bCol] = tv;
        }
        __syncthreads();

#pragma unroll
        for (int kk = 0; kk < TBK; kk += 8) {
            uint32_t af[4][4], bf[4][2];
#pragma unroll
            for (int mt = 0; mt < 4; mt++) {
                const int rm = warp_m + mt * 16;
                af[mt][0] = As[kk + tig    ][rm + g    ];
                af[mt][1] = As[kk + tig    ][rm + g + 8];
                af[mt][2] = As[kk + tig + 4][rm + g    ];
                af[mt][3] = As[kk + tig + 4][rm + g + 8];
            }
#pragma unroll
            for (int nt = 0; nt < 4; nt++) {
                const int cn = warp_n + nt * 8;
                bf[nt][0] = Bs[kk + tig    ][cn + g];
                bf[nt][1] = Bs[kk + tig + 4][cn + g];
            }
#pragma unroll
            for (int mt = 0; mt < 4; mt++)
#pragma unroll
                for (int nt = 0; nt < 4; nt++)
                    mma_tf32(acc[mt][nt][0], acc[mt][nt][1],
                             acc[mt][nt][2], acc[mt][nt][3],
                             af[mt][0], af[mt][1], af[mt][2], af[mt][3],
                             bf[nt][0], bf[nt][1]);
        }
        __syncthreads();
    }

#pragma unroll
    for (int mt = 0; mt < 4; mt++) {
#pragma unroll
        for (int nt = 0; nt < 4; nt++) {
            const int col = bcol0 + warp_n + nt * 8 + tig * 2;
            const float b0 = bias[col], b1 = bias[col + 1];
            const size_t r0 = (size_t)(brow0 + warp_m + mt * 16 + g);
            const size_t r1 = r0 + 8;
            float2 v0 = make_float2(acc[mt][nt][0] + b0, acc[mt][nt][1] + b1);
            float2 v1 = make_float2(acc[mt][nt][2] + b0, acc[mt][nt][3] + b1);
            *(float2*)(C + r0 * Nd + col) = v0;
            *(float2*)(C + r1 * Nd + col) = v1;
        }
    }
}

// ================= RoPE (rotation only; q scale applied in flash) =================
__global__ void rope_kernel(float* __restrict__ q, float* __restrict__ k,
                            const float* __restrict__ pos_enc)
{
    const int total = B * N * H * (RD / 2);
    int idx = blockIdx.x * blockDim.x + threadIdx.x;
    if (idx >= total) return;

    const int p = idx % (RD / 2);
    const int h = (idx / (RD / 2)) % H;
    const int n = (idx / ((RD / 2) * H)) % N;
    const int b = idx / ((RD / 2) * H * N);

    const float pe0 = pos_enc[n * RD + 2 * p];
    const float pe1 = pos_enc[n * RD + 2 * p + 1];
    const float c0 = cosf(pe0), s0 = sinf(pe0);
    const float c1 = cosf(pe1), s1 = sinf(pe1);

    const size_t base = ((size_t)(b * N + n)) * D + h * HD + 2 * p;

    float q0 = q[base], q1 = q[base + 1];
    q[base]     = q0 * c0 - q1 * s0;
    q[base + 1] = q1 * c1 + q0 * s1;

    float k0 = k[base], k1 = k[base + 1];
    k[base]     = k0 * c0 - k1 * s0;
    k[base + 1] = k1 * c1 + k0 * s1;
}

// ================= Flash attention (TF32 tensor core, causal) =================
// 64x64 tiles, 4 warps (128 thr), warp owns 16 q-rows.
// Smem layouts (uint32 tf32 unless noted), stride 72 => conflict-free frag loads:
//   Qs[d][row]   (A-frag for QK)
//   Ks[d][key]   (B-frag for QK)
//   Vs[key][d]   (B-frag for PV)
//   Ps[key][row] (A-frag for PV; written post-softmax)
constexpr int FSTR = 72;
constexpr int FLASH_SMEM = (4 * 64 * FSTR) * (int)sizeof(uint32_t) + 64 * (int)sizeof(float);

__global__ __launch_bounds__(128) void flash_tc_kernel(
    const float* __restrict__ q, const float* __restrict__ k,
    const float* __restrict__ v, const unsigned char* __restrict__ pad,
    float* __restrict__ o)
{
    extern __shared__ uint32_t smu[];
    uint32_t* Qs = smu;                    // [64][FSTR]
    uint32_t* Ks = Qs + 64 * FSTR;
    uint32_t* Vs = Ks + 64 * FSTR;
    uint32_t* Ps = Vs + 64 * FSTR;
    float*    Padv = (float*)(Ps + 64 * FSTR);  // [64] +3e38 or -3e38

    const int qt = blockIdx.x;
    const int h  = blockIdx.y;
    const int b  = blockIdx.z;
    const int qi0 = qt * 64;

    const int tid  = threadIdx.x;
    const int wid  = tid >> 5;
    const int lane = tid & 31;
    const int g    = lane >> 2;
    const int tig  = lane & 3;
    const int warp_m = wid * 16;

    // ---- load Q tile (scaled), transposed into Qs[d][row] ----
    const size_t qbase = ((size_t)(b * N + qi0)) * D + h * HD;
    for (int i = tid; i < 64 * 16; i += 128) {
        const int r  = i >> 4;
        const int c4 = (i & 15) * 4;
        float4 qv = *(const float4*)(q + qbase + (size_t)r * D + c4);
        Qs[(c4 + 0) * FSTR + r] = f32_to_tf32(qv.x * 0.125f);
        Qs[(c4 + 1) * FSTR + r] = f32_to_tf32(qv.y * 0.125f);
        Qs[(c4 + 2) * FSTR + r] = f32_to_tf32(qv.z * 0.125f);
        Qs[(c4 + 3) * FSTR + r] = f32_to_tf32(qv.w * 0.125f);
    }

    // state: rows g and g+8 (within warp's 16-row stripe)
    float m0 = -1e30f, m1 = -1e30f, l0 = 0.0f, l1 = 0.0f;
    float oacc[8][4];
#pragma unroll
    for (int nt = 0; nt < 8; nt++)
#pragma unroll
        for (int r = 0; r < 4; r++) oacc[nt][r] = 0.0f;

    const int ktiles = qt + 1;
    for (int kt = 0; kt < ktiles; kt++) {
        const int kj0 = kt * 64;
        const size_t kbase = ((size_t)(b * N + kj0)) * D + h * HD;

        // K -> Ks[d][key] (transposed), V -> Vs[key][d] (natural)
        for (int i = tid; i < 64 * 16; i += 128) {
            const int r  = i >> 4;
            const int c4 = (i & 15) * 4;
            float4 kv = *(const float4*)(k + kbase + (size_t)r * D + c4);
            Ks[(c4 + 0) * FSTR + r] = f32_to_tf32(kv.x);
            Ks[(c4 + 1) * FSTR + r] = f32_to_tf32(kv.y);
            Ks[(c4 + 2) * FSTR + r] = f32_to_tf32(kv.z);
            Ks[(c4 + 3) * FSTR + r] = f32_to_tf32(kv.w);

            float4 vv = *(const float4*)(v + kbase + (size_t)r * D + c4);
            uint4 tv;
            tv.x = f32_to_tf32(vv.x);
            tv.y = f32_to_tf32(vv.y);
            tv.z = f32_to_tf32(vv.z);
            tv.w = f32_to_tf32(vv.w);
            *(uint4*)&Vs[r * FSTR + c4] = tv;
        }
        if (tid < 64)
            Padv[tid] = pad[b * N + kj0 + tid] ? -3e38f : 3e38f;
        __syncthreads();

        // ---- S = Q K^T ----
        float s[8][4];
#pragma unroll
        for (int nt = 0; nt < 8; nt++)
#pragma unroll
            for (int r = 0; r < 4; r++) s[nt][r] = 0.0f;

#pragma unroll
        for (int kk = 0; kk < 64; kk += 8) {
            uint32_t a0 = Qs[(kk + tig    ) * FSTR + warp_m + g    ];
            uint32_t a1 = Qs[(kk + tig    ) * FSTR + warp_m + g + 8];
            uint32_t a2 = Qs[(kk + tig + 4) * FSTR + warp_m + g    ];
            uint32_t a3 = Qs[(kk + tig + 4) * FSTR + warp_m + g + 8];
#pragma unroll
            for (int nt = 0; nt < 8; nt++) {
                uint32_t b0 = Ks[(kk + tig    ) * FSTR + nt * 8 + g];
                uint32_t b1 = Ks[(kk + tig + 4) * FSTR + nt * 8 + g];
                mma_tf32(s[nt][0], s[nt][1], s[nt][2], s[nt][3],
                         a0, a1, a2, a3, b0, b1);
            }
        }

        // ---- mask ----
        const int row0 = qi0 + warp_m + g;       // global q row for regs 0,1
        const int row1 = row0 + 8;               // for regs 2,3
#pragma unroll
        for (int nt = 0; nt < 8; nt++) {
            const int c0 = nt * 8 + tig * 2;
            const float p0 = Padv[c0], p1 = Padv[c0 + 1];
            s[nt][0] = fminf(s[nt][0], p0);
            s[nt][1] = fminf(s[nt][1], p1);
            s[nt][2] = fminf(s[nt][2], p0);
            s[nt][3] = fminf(s[nt][3], p1);
        }
        if (kt == qt) {  // diagonal tile: causal partial mask
#pragma unroll
            for (int nt = 0; nt < 8; nt++) {
                const int c0 = kj0 + nt * 8 + tig * 2;
                if (c0     > row0) s[nt][0] = -1e30f;
                if (c0 + 1 > row0) s[nt][1] = -1e30f;
                if (c0     > row1) s[nt][2] = -1e30f;
                if (c0 + 1 > row1) s[nt][3] = -1e30f;
            }
        }

        // ---- online softmax (row spread over 4 lanes: xor 1,2) ----
        float mx0 = -1e30f, mx1 = -1e30f;
#pragma unroll
        for (int nt = 0; nt < 8; nt++) {
            mx0 = fmaxf(mx0, fmaxf(s[nt][0], s[nt][1]));
            mx1 = fmaxf(mx1, fmaxf(s[nt][2], s[nt][3]));
        }
        mx0 = fmaxf(mx0, __shfl_xor_sync(0xffffffffu, mx0, 1));
        mx0 = fmaxf(mx0, __shfl_xor_sync(0xffffffffu, mx0, 2));
        mx1 = fmaxf(mx1, __shfl_xor_sync(0xffffffffu, mx1, 1));
        mx1 = fmaxf(mx1, __shfl_xor_sync(0xffffffffu, mx1, 2));

        const float mn0 = fmaxf(m0, mx0);
        const float mn1 = fmaxf(m1, mx1);
        const float al0 = __expf(m0 - mn0);
        const float al1 = __expf(m1 - mn1);
        m0 = mn0; m1 = mn1;

        float sum0 = 0.0f, sum1 = 0.0f;
#pragma unroll
        for (int nt = 0; nt < 8; nt++) {
            s[nt][0] = __expf(s[nt][0] - mn0);
            s[nt][1] = __expf(s[nt][1] - mn0);
            s[nt][2] = __expf(s[nt][2] - mn1);
            s[nt][3] = __expf(s[nt][3] - mn1);
            sum0 += s[nt][0] + s[nt][1];
            sum1 += s[nt][2] + s[nt][3];
        }
        sum0 += __shfl_xor_sync(0xffffffffu, sum0, 1);
        sum0 += __shfl_xor_sync(0xffffffffu, sum0, 2);
        sum1 += __shfl_xor_sync(0xffffffffu, sum1, 1);
        sum1 += __shfl_xor_sync(0xffffffffu, sum1, 2);
        l0 = l0 * al0 + sum0;
        l1 = l1 * al1 + sum1;

#pragma unroll
        for (int nt = 0; nt < 8; nt++) {
#pragma unroll
            for (int r = 0; r < 4; r++) oacc[nt][r] *= (r < 2 ? al0 : al1);
        }

        // ---- P -> smem (Ps[key][row], tf32) ----
#pragma unroll
        for (int nt = 0; nt < 8; nt++) {
            const int c0 = nt * 8 + tig * 2;
            Ps[(c0    ) * FSTR + warp_m + g    ] = f32_to_tf32(s[nt][0]);
            Ps[(c0 + 1) * FSTR + warp_m + g    ] = f32_to_tf32(s[nt][1]);
            Ps[(c0    ) * FSTR + warp_m + g + 8] = f32_to_tf32(s[nt][2]);
            Ps[(c0 + 1) * FSTR + warp_m + g + 8] = f32_to_tf32(s[nt][3]);
        }
        __syncwarp();   // Ps rows are warp-private (both write and read)

        // ---- O += P V ----
#pragma unroll
        for (int kk = 0; kk < 64; kk += 8) {
            uint32_t a0 = Ps[(kk + tig    ) * FSTR + warp_m + g    ];
            uint32_t a1 = Ps[(kk + tig    ) * FSTR + warp_m + g + 8];
            uint32_t a2 = Ps[(kk + tig + 4) * FSTR + warp_m + g    ];
            uint32_t a3 = Ps[(kk + tig + 4) * FSTR + warp_m + g + 8];
#pragma unroll
            for (int nt = 0; nt < 8; nt++) {
                uint32_t b0 = Vs[(kk + tig    ) * FSTR + nt * 8 + g];
                uint32_t b1 = Vs[(kk + tig + 4) * FSTR + nt * 8 + g];
                mma_tf32(oacc[nt][0], oacc[nt][1], oacc[nt][2], oacc[nt][3],
                         a0, a1, a2, a3, b0, b1);
            }
        }
        __syncthreads();  // all warps done with Ks/Vs before next tile load
    }

    // ---- write O ----
    const float il0 = 1.0f / l0;
    const float il1 = 1.0f / l1;
    const size_t ob0 = ((size_t)(b * N + qi0 + warp_m + g    )) * D + h * HD;
    const size_t ob1 = ((size_t)(b * N + qi0 + warp_m + g + 8)) * D + h * HD;
#pragma unroll
    for (int nt = 0; nt < 8; nt++) {
        const int c0 = nt * 8 + tig * 2;
        *(float2*)(o + ob0 + c0) = make_float2(oacc[nt][0] * il0, oacc[nt][1] * il0);
        *(float2*)(o + ob1 + c0) = make_float2(oacc[nt][2] * il1, oacc[nt][3] * il1);
    }
}

}  // namespace

extern "C" void kernel_launch(void* const* d_in, const int* in_sizes, int n_in,
                              void* d_out, int out_size)
{
    const float* x_q  = (const float*)d_in[0];
    const float* x_kv = (const float*)d_in[1];
    const float* pos_enc = (const float*)d_in[2];
    const float* Wq = (const float*)d_in[3];
    const float* bq = (const float*)d_in[4];
    const float* Wk = (const float*)d_in[5];
    const float* bk = (const float*)d_in[6];
    const float* Wv = (const float*)d_in[7];
    const float* bv = (const float*)d_in[8];
    const float* Wo = (const float*)d_in[9];
    const float* bo = (const float*)d_in[10];
    const unsigned char* pad = (const unsigned char*)d_in[11];
    float* out = (float*)d_out;

    float *q, *k, *v, *o;
    cudaGetSymbolAddress((void**)&q, g_q);
    cudaGetSymbolAddress((void**)&k, g_k);
    cudaGetSymbolAddress((void**)&v, g_v);
    cudaGetSymbolAddress((void**)&o, g_o);

    const dim3 gemm_grid(D / TBN, M / TBM);  // (8, 64)

    tf32_gemm_bias_kernel<<<gemm_grid, 256>>>(x_q,  Wq, bq, q, D, D);
    tf32_gemm_bias_kernel<<<gemm_grid, 256>>>(x_kv, Wk, bk, k, D, D);
    tf32_gemm_bias_kernel<<<gemm_grid, 256>>>(x_kv, Wv, bv, v, D, D);

    const int rope_total = B * N * H * (RD / 2);
    rope_kernel<<<(rope_total + 255) / 256, 256>>>(q, k, pos_enc);

    cudaFuncSetAttribute(flash_tc_kernel,
                         cudaFuncAttributeMaxDynamicSharedMemorySize, FLASH_SMEM);
    flash_tc_kernel<<<dim3(N / 64, H, B), 128, FLASH_SMEM>>>(q, k, v, pad, o);

    tf32_gemm_bias_kernel<<<gemm_grid, 256>>>(o, Wo, bo, out, D, D);
}